// round 12
// baseline (speedup 1.0000x reference)
#include <cuda_runtime.h>
#include <cuda_bf16.h>
#include <cstdint>

#define NN 50000
#define NE 800000
#define DD 128
#define NC 10
#define NG 64
#define NB 196   // ceil(NN/256)

// ---------------- scratch (static device globals; no runtime alloc) --------
__device__ unsigned g_bh [NN * DD / 2];  // GEMM1 output xw1 as bf16x2
__device__ unsigned g_bh2[NN * DD / 2];  // GEMM2 output dis*xw2 as bf16x2
__device__ float g_buf1[NN * DD];        // aggregation output h' (relu, fp32)
__device__ float g_dis[NN];
__device__ int   g_deg[NN];
__device__ int   g_off[NN + 1];
__device__ int   g_cur[NN];
__device__ int   g_csr[NE];
__device__ int   g_bsum[NB];
__device__ int   g_boff[NB];
__device__ int   g_anyodd;          // 0 => indices are int64, nonzero => int32

__device__ __forceinline__ int ld_idx(const void* p, long long i, int is64) {
    return is64 ? (int)((const long long*)p)[i] : ((const int*)p)[i];
}
__device__ __forceinline__ unsigned pack_bf(float a, float b) {
    __nv_bfloat162 h = __floats2bfloat162_rn(a, b);
    return *(unsigned*)&h;
}
__device__ __forceinline__ float2 unpack_bf(unsigned u) {
    return __bfloat1622float2(*(__nv_bfloat162*)&u);
}

// ---------------- setup: zero deg + dtype detect (fused) --------------------
__global__ void k_init(const void* ei) {
    int i = blockIdx.x * blockDim.x + threadIdx.x;
    if (i < NN) g_deg[i] = 0;
    if (blockIdx.x == 0) {
        __shared__ int sm[256];
        int any = 0;
        for (int j = threadIdx.x; j < 4096; j += 256)
            any |= ((const int*)ei)[2 * j + 1];
        sm[threadIdx.x] = any;
        __syncthreads();
        for (int s = 128; s > 0; s >>= 1) {
            if (threadIdx.x < s) sm[threadIdx.x] |= sm[threadIdx.x + s];
            __syncthreads();
        }
        if (threadIdx.x == 0) g_anyodd = sm[0];
    }
}

__global__ void k_deg(const void* ei) {
    int e = blockIdx.x * blockDim.x + threadIdx.x;
    if (e >= NE) return;
    int is64 = (g_anyodd == 0);
    int c = ld_idx(ei, (long long)NE + e, is64);
    atomicAdd(&g_deg[c], 1);
}

// ---------------- 3-stage parallel scan of g_deg ----------------------------
__global__ void k_scanA() {
    __shared__ int sm[256];
    int t = threadIdx.x;
    int i = blockIdx.x * 256 + t;
    sm[t] = (i < NN) ? g_deg[i] : 0;
    __syncthreads();
    for (int s = 128; s > 0; s >>= 1) {
        if (t < s) sm[t] += sm[t + s];
        __syncthreads();
    }
    if (t == 0) g_bsum[blockIdx.x] = sm[0];
}

__global__ void k_scanB() {
    __shared__ int sm[256];
    int t = threadIdx.x;
    int v = (t < NB) ? g_bsum[t] : 0;
    sm[t] = v;
    __syncthreads();
    for (int off = 1; off < 256; off <<= 1) {
        int u = (t >= off) ? sm[t - off] : 0;
        __syncthreads();
        sm[t] += u;
        __syncthreads();
    }
    if (t < NB) g_boff[t] = sm[t] - v;   // exclusive
}

__global__ void k_scanC() {
    __shared__ int sm[256];
    int t = threadIdx.x;
    int i = blockIdx.x * 256 + t;
    int d = (i < NN) ? g_deg[i] : 0;
    sm[t] = d;
    __syncthreads();
    for (int off = 1; off < 256; off <<= 1) {
        int u = (t >= off) ? sm[t - off] : 0;
        __syncthreads();
        sm[t] += u;
        __syncthreads();
    }
    int off = g_boff[blockIdx.x] + sm[t] - d;   // exclusive prefix
    if (i < NN) {
        g_off[i] = off;
        g_cur[i] = off;
        g_dis[i] = rsqrtf((float)(d + 1));      // +1 self-loop
    }
    if (i == NN - 1) g_off[NN] = off + d;
}

__global__ void k_scatter(const void* ei) {
    int e = blockIdx.x * blockDim.x + threadIdx.x;
    if (e >= NE) return;
    int is64 = (g_anyodd == 0);
    int r = ld_idx(ei, e, is64);
    int c = ld_idx(ei, (long long)NE + e, is64);
    int pos = atomicAdd(&g_cur[c], 1);
    g_csr[pos] = r;
}

// ---------------- FFMA GEMM, bf16 output, chunkable -------------------------
// layer==0: A = x, dst = g_bh, RAW xw (no dis -> no setup dependency).
// layer==1: A = g_buf1, dst = g_bh2, scaled by dis.
#define GM 64
__global__ void __launch_bounds__(256) k_gemm(const float* __restrict__ x_ext,
                                              const float* __restrict__ W,
                                              int layer, int mblk0) {
    __shared__ float Ws[32][DD];      // [k][n], rows 16B-aligned
    __shared__ float As[32][GM + 4];  // [k][m], 272B rows (16B-aligned)
    const float* __restrict__ A = (layer == 0) ? x_ext : g_buf1;
    unsigned* __restrict__ dst = (layer == 0) ? g_bh : g_bh2;

    int t = threadIdx.x;
    int m0 = (blockIdx.x + mblk0) * GM;
    int tr = t >> 5;   // 0..7 (warp-uniform)
    int tc = t & 31;   // 0..31

    float4 acc[8];
#pragma unroll
    for (int i = 0; i < 8; i++) acc[i] = make_float4(0.f, 0.f, 0.f, 0.f);

    for (int k0 = 0; k0 < DD; k0 += 32) {
        // stage A tile [64 rows x 32 k] transposed into As[k][m]
#pragma unroll
        for (int q = 0; q < 2; q++) {
            int id = q * 256 + t;      // 0..511
            int r  = id >> 3;          // 0..63
            int kq = id & 7;           // float4 within 32-k row
            int gm = m0 + r;
            float4 v = make_float4(0.f, 0.f, 0.f, 0.f);
            if (gm < NN) v = *(const float4*)&A[(size_t)gm * DD + k0 + kq * 4];
            As[kq * 4 + 0][r] = v.x;
            As[kq * 4 + 1][r] = v.y;
            As[kq * 4 + 2][r] = v.z;
            As[kq * 4 + 3][r] = v.w;
        }
        // stage W tile [32 k x 128 n]
#pragma unroll
        for (int q = 0; q < 4; q++) {
            int id = q * 256 + t;      // 0..1023
            int kr = id >> 5;          // 0..31
            int cq = id & 31;          // 0..31
            *(float4*)&Ws[kr][cq * 4] =
                *(const float4*)&W[(size_t)(k0 + kr) * DD + cq * 4];
        }
        __syncthreads();

#pragma unroll
        for (int kk = 0; kk < 32; kk++) {
            float4 w = *(const float4*)&Ws[kk][tc * 4];
            float4 a03 = *(const float4*)&As[kk][tr * 8];      // broadcast
            float4 a47 = *(const float4*)&As[kk][tr * 8 + 4];  // broadcast
            float am[8] = {a03.x, a03.y, a03.z, a03.w,
                           a47.x, a47.y, a47.z, a47.w};
#pragma unroll
            for (int i = 0; i < 8; i++) {
                acc[i].x += am[i] * w.x;
                acc[i].y += am[i] * w.y;
                acc[i].z += am[i] * w.z;
                acc[i].w += am[i] * w.w;
            }
        }
        __syncthreads();
    }

#pragma unroll
    for (int i = 0; i < 8; i++) {
        int gm = m0 + tr * 8 + i;
        if (gm < NN) {
            float ds = (layer == 0) ? 1.f : g_dis[gm];
            uint2 pk;
            pk.x = pack_bf(ds * acc[i].x, ds * acc[i].y);
            pk.y = pack_bf(ds * acc[i].z, ds * acc[i].w);
            *(uint2*)&dst[(size_t)gm * 64 + tc * 2] = pk;
        }
    }
}

// ---------------- aggregation (bf16 gathers, unroll-8/4 MLP, chunkable) -----
// mode 0 (src g_bh, raw xw):   o = relu(dis[c]*(dis[c]*y[c] + sum dis[r]*y[r]) + b)
// mode 1 (src g_bh2, dis*xw):  o = relu(dis[c]*(y[c] + sum y[r]) + b)
__global__ void __launch_bounds__(256) k_agg(const float* __restrict__ bias,
                                             int mode, int nbeg, int nend) {
    int w = nbeg + ((blockIdx.x * blockDim.x + threadIdx.x) >> 5);
    int lane = threadIdx.x & 31;
    if (w >= nend) return;
    const unsigned* __restrict__ src = (mode == 0) ? g_bh : g_bh2;
    float ds = g_dis[w];

    uint2 sv = *(const uint2*)&src[(size_t)w * 64 + lane * 2];
    float2 s0 = unpack_bf(sv.x), s1 = unpack_bf(sv.y);
    float4 a0 = make_float4(s0.x, s0.y, s1.x, s1.y);   // self-loop term
    if (mode == 0) { a0.x *= ds; a0.y *= ds; a0.z *= ds; a0.w *= ds; }
    float4 a1 = make_float4(0.f, 0.f, 0.f, 0.f);
    float4 a2 = make_float4(0.f, 0.f, 0.f, 0.f);
    float4 a3 = make_float4(0.f, 0.f, 0.f, 0.f);

    int p = g_off[w];
    int e2 = g_off[w + 1];
    // unroll-8 main loop: 8 independent LDG.64 in flight per warp
    for (; p + 7 < e2; p += 8) {
        int rr[8];
#pragma unroll
        for (int j = 0; j < 8; j++) rr[j] = g_csr[p + j];
        uint2 uu[8];
#pragma unroll
        for (int j = 0; j < 8; j++)
            uu[j] = *(const uint2*)&src[(size_t)rr[j] * 64 + lane * 2];
#pragma unroll
        for (int j = 0; j < 8; j++) {
            float d = (mode == 0) ? g_dis[rr[j]] : 1.f;
            float2 fa = unpack_bf(uu[j].x), fb = unpack_bf(uu[j].y);
            float4* ac = (j & 3) == 0 ? &a0 : (j & 3) == 1 ? &a1
                       : (j & 3) == 2 ? &a2 : &a3;
            ac->x += d * fa.x; ac->y += d * fa.y;
            ac->z += d * fb.x; ac->w += d * fb.y;
        }
    }
    // unroll-4 tail
    if (p + 3 < e2) {
        int rr[4];
#pragma unroll
        for (int j = 0; j < 4; j++) rr[j] = g_csr[p + j];
        uint2 uu[4];
#pragma unroll
        for (int j = 0; j < 4; j++)
            uu[j] = *(const uint2*)&src[(size_t)rr[j] * 64 + lane * 2];
#pragma unroll
        for (int j = 0; j < 4; j++) {
            float d = (mode == 0) ? g_dis[rr[j]] : 1.f;
            float2 fa = unpack_bf(uu[j].x), fb = unpack_bf(uu[j].y);
            float4* ac = j == 0 ? &a0 : j == 1 ? &a1 : j == 2 ? &a2 : &a3;
            ac->x += d * fa.x; ac->y += d * fa.y;
            ac->z += d * fb.x; ac->w += d * fb.y;
        }
        p += 4;
    }
    for (; p < e2; p++) {
        int r0 = g_csr[p];
        uint2 u0 = *(const uint2*)&src[(size_t)r0 * 64 + lane * 2];
        float2 f0a = unpack_bf(u0.x), f0b = unpack_bf(u0.y);
        float d0 = (mode == 0) ? g_dis[r0] : 1.f;
        a0.x += d0 * f0a.x; a0.y += d0 * f0a.y;
        a0.z += d0 * f0b.x; a0.w += d0 * f0b.y;
    }
    float4 b = ((const float4*)bias)[lane];
    float4 o;
    o.x = fmaxf(ds * ((a0.x + a1.x) + (a2.x + a3.x)) + b.x, 0.f);
    o.y = fmaxf(ds * ((a0.y + a1.y) + (a2.y + a3.y)) + b.y, 0.f);
    o.z = fmaxf(ds * ((a0.z + a1.z) + (a2.z + a3.z)) + b.z, 0.f);
    o.w = fmaxf(ds * ((a0.w + a1.w) + (a2.w + a3.w)) + b.w, 0.f);
    ((float4*)g_buf1)[(size_t)w * 32 + lane] = o;
}

// ---------------- fused pool + FC + log_softmax (per-graph independent) -----
__global__ void k_poolhead(const void* batch,
                           const float* __restrict__ Wfc,
                           const float* __restrict__ bfc,
                           float* __restrict__ out) {
    __shared__ float red[4][DD];
    __shared__ float pool[DD];
    __shared__ float lg[NC];
    int g = blockIdx.x;
    int is64 = (g_anyodd == 0);
    int lo = 0, hi = NN;
    while (lo < hi) {
        int mid = (lo + hi) >> 1;
        if (ld_idx(batch, mid, is64) < g) lo = mid + 1; else hi = mid;
    }
    int start = lo;
    hi = NN;
    while (lo < hi) {
        int mid = (lo + hi) >> 1;
        if (ld_idx(batch, mid, is64) <= g) lo = mid + 1; else hi = mid;
    }
    int end = lo;

    int d = threadIdx.x & 127;
    int rg = threadIdx.x >> 7;   // 0..3
    const float* __restrict__ h = g_buf1;
    float s = 0.f;
    for (int i = start + rg; i < end; i += 4) s += h[(size_t)i * DD + d];
    red[rg][d] = s;
    __syncthreads();
    if (rg == 0) {
        float inv = 1.f / fmaxf((float)(end - start), 1.f);
        pool[d] = ((red[0][d] + red[1][d]) + (red[2][d] + red[3][d])) * inv;
    }
    __syncthreads();
    if (threadIdx.x < NC) {
        int c = threadIdx.x;
        float acc = bfc[c];
#pragma unroll 4
        for (int dd2 = 0; dd2 < DD; dd2++)
            acc += pool[dd2] * Wfc[dd2 * NC + c];
        lg[c] = acc;
    }
    __syncthreads();
    if (threadIdx.x < NC) {
        int c = threadIdx.x;
        float m = -1e30f;
#pragma unroll
        for (int k = 0; k < NC; k++) m = fmaxf(m, lg[k]);
        float sum = 0.f;
#pragma unroll
        for (int k = 0; k < NC; k++) sum += expf(lg[k] - m);
        out[g * NC + c] = lg[c] - m - logf(sum);
    }
}

// ---------------- launch ----------------------------------------------------
extern "C" void kernel_launch(void* const* d_in, const int* in_sizes, int n_in,
                              void* d_out, int out_size) {
    (void)in_sizes; (void)n_in; (void)out_size;
    const float* x   = (const float*)d_in[0];
    const void*  ei  = d_in[1];
    const void*  bat = d_in[2];
    const float* W1  = (const float*)d_in[3];
    const float* b1  = (const float*)d_in[4];
    const float* W2  = (const float*)d_in[5];
    const float* b2  = (const float*)d_in[6];
    const float* Wfc = (const float*)d_in[7];
    const float* bfc = (const float*)d_in[8];
    float* out = (float*)d_out;

    // Side stream + events, created once on the (uncaptured) first call and
    // reused thereafter; the launched work is identical on every call.
    static cudaStream_t s2 = nullptr;
    static cudaEvent_t ev_fork = nullptr, ev_join = nullptr, ev_j2 = nullptr;
    static cudaEvent_t evA[4] = {nullptr, nullptr, nullptr, nullptr};
    if (s2 == nullptr) {
        cudaStreamCreateWithFlags(&s2, cudaStreamNonBlocking);
        cudaEventCreateWithFlags(&ev_fork, cudaEventDisableTiming);
        cudaEventCreateWithFlags(&ev_join, cudaEventDisableTiming);
        cudaEventCreateWithFlags(&ev_j2, cudaEventDisableTiming);
        for (int c = 0; c < 4; c++)
            cudaEventCreateWithFlags(&evA[c], cudaEventDisableTiming);
    }

    const int NBLK = (NN + GM - 1) / GM;            // 782
    static const int cb[5] = {0, 196, 392, 588, NBLK};   // gemm block chunks
    static const int rb[5] = {0, 12544, 25088, 37632, NN};

    // fork: GEMM1 (raw xw1, no setup dependency) on s2 || CSR build on main
    cudaEventRecord(ev_fork, 0);
    cudaStreamWaitEvent(s2, ev_fork, 0);
    k_gemm<<<NBLK, 256, 0, s2>>>(x, W1, 0, 0);      // xw1 -> g_bh (raw)
    cudaEventRecord(ev_join, s2);

    k_init<<<NB, 256>>>(ei);
    k_deg<<<(NE + 255) / 256, 256>>>(ei);
    k_scanA<<<NB, 256>>>();
    k_scanB<<<1, 256>>>();
    k_scanC<<<NB, 256>>>();
    k_scatter<<<(NE + 255) / 256, 256>>>(ei);

    // join: agg1 needs CSR + dis (main) AND g_bh (s2)
    cudaStreamWaitEvent(0, ev_join, 0);

    // pipelined agg1 (main) -> GEMM2 chunks (s2, writes g_bh2)
    for (int c = 0; c < 4; c++) {
        int rows = rb[c + 1] - rb[c];
        k_agg<<<(rows * 32 + 255) / 256, 256>>>(b1, 0, rb[c], rb[c + 1]);
        cudaEventRecord(evA[c], 0);
        cudaStreamWaitEvent(s2, evA[c], 0);
        k_gemm<<<cb[c + 1] - cb[c], 256, 0, s2>>>(x, W2, 1, cb[c]);
    }
    cudaEventRecord(ev_j2, s2);
    cudaStreamWaitEvent(0, ev_j2, 0);

    k_agg<<<(NN * 32 + 255) / 256, 256>>>(b2, 1, 0, NN);   // h2 -> buf1
    k_poolhead<<<NG, 512>>>(bat, Wfc, bfc, out);
}

// round 14
// speedup vs baseline: 1.1336x; 1.1336x over previous
#include <cuda_runtime.h>
#include <cuda_bf16.h>
#include <cstdint>

#define NN 50000
#define NE 800000
#define DD 128
#define NC 10
#define NG 64
#define NB 196   // ceil(NN/256)

// ---------------- scratch (static device globals; no runtime alloc) --------
__device__ unsigned g_bh[NN * DD / 2];  // GEMM output y as bf16x2 (8B/4 dims)
__device__ float g_buf1[NN * DD];       // aggregation output h' (relu, fp32)
__device__ float g_dis[NN];
__device__ int   g_deg[NN];
__device__ int   g_off[NN + 1];
__device__ int   g_cur[NN];
__device__ int   g_csr[NE];
__device__ int   g_bsum[NB];
__device__ int   g_boff[NB];
__device__ int   g_anyodd;          // 0 => indices are int64, nonzero => int32

__device__ __forceinline__ int ld_idx(const void* p, long long i, int is64) {
    return is64 ? (int)((const long long*)p)[i] : ((const int*)p)[i];
}
__device__ __forceinline__ unsigned pack_bf(float a, float b) {
    __nv_bfloat162 h = __floats2bfloat162_rn(a, b);
    return *(unsigned*)&h;
}
__device__ __forceinline__ float2 unpack_bf(unsigned u) {
    return __bfloat1622float2(*(__nv_bfloat162*)&u);
}

// ---------------- setup: zero deg + dtype detect (fused) --------------------
__global__ void k_init(const void* ei) {
    int i = blockIdx.x * blockDim.x + threadIdx.x;
    if (i < NN) g_deg[i] = 0;
    if (blockIdx.x == 0) {
        __shared__ int sm[256];
        int any = 0;
        for (int j = threadIdx.x; j < 4096; j += 256)
            any |= ((const int*)ei)[2 * j + 1];
        sm[threadIdx.x] = any;
        __syncthreads();
        for (int s = 128; s > 0; s >>= 1) {
            if (threadIdx.x < s) sm[threadIdx.x] |= sm[threadIdx.x + s];
            __syncthreads();
        }
        if (threadIdx.x == 0) g_anyodd = sm[0];
    }
}

__global__ void k_deg(const void* ei) {
    int e = blockIdx.x * blockDim.x + threadIdx.x;
    if (e >= NE) return;
    int is64 = (g_anyodd == 0);
    int c = ld_idx(ei, (long long)NE + e, is64);
    atomicAdd(&g_deg[c], 1);
}

// ---------------- 3-stage parallel scan of g_deg ----------------------------
__global__ void k_scanA() {
    __shared__ int sm[256];
    int t = threadIdx.x;
    int i = blockIdx.x * 256 + t;
    sm[t] = (i < NN) ? g_deg[i] : 0;
    __syncthreads();
    for (int s = 128; s > 0; s >>= 1) {
        if (t < s) sm[t] += sm[t + s];
        __syncthreads();
    }
    if (t == 0) g_bsum[blockIdx.x] = sm[0];
}

__global__ void k_scanB() {
    __shared__ int sm[256];
    int t = threadIdx.x;
    int v = (t < NB) ? g_bsum[t] : 0;
    sm[t] = v;
    __syncthreads();
    for (int off = 1; off < 256; off <<= 1) {
        int u = (t >= off) ? sm[t - off] : 0;
        __syncthreads();
        sm[t] += u;
        __syncthreads();
    }
    if (t < NB) g_boff[t] = sm[t] - v;   // exclusive
}

__global__ void k_scanC() {
    __shared__ int sm[256];
    int t = threadIdx.x;
    int i = blockIdx.x * 256 + t;
    int d = (i < NN) ? g_deg[i] : 0;
    sm[t] = d;
    __syncthreads();
    for (int off = 1; off < 256; off <<= 1) {
        int u = (t >= off) ? sm[t - off] : 0;
        __syncthreads();
        sm[t] += u;
        __syncthreads();
    }
    int off = g_boff[blockIdx.x] + sm[t] - d;   // exclusive prefix
    if (i < NN) {
        g_off[i] = off;
        g_cur[i] = off;
        g_dis[i] = rsqrtf((float)(d + 1));      // +1 self-loop
    }
    if (i == NN - 1) g_off[NN] = off + d;
}

__global__ void k_scatter(const void* ei) {
    int e = blockIdx.x * blockDim.x + threadIdx.x;
    if (e >= NE) return;
    int is64 = (g_anyodd == 0);
    int r = ld_idx(ei, e, is64);
    int c = ld_idx(ei, (long long)NE + e, is64);
    int pos = atomicAdd(&g_cur[c], 1);
    g_csr[pos] = r;
}

// ---------------- FFMA GEMM, bf16 output, LDS.128 A reads -------------------
// layer==0: A = x, stores RAW xw as bf16 (no dis -> no setup dependency).
// layer==1: A = g_buf1, stores dis*xw as bf16.
#define GM 64
__global__ void __launch_bounds__(256) k_gemm(const float* __restrict__ x_ext,
                                              const float* __restrict__ W,
                                              int layer) {
    __shared__ float Ws[32][DD];      // [k][n], rows 16B-aligned
    __shared__ float As[32][GM + 4];  // [k][m], 272B rows (16B-aligned)
    const float* __restrict__ A = (layer == 0) ? x_ext : g_buf1;

    int t = threadIdx.x;
    int m0 = blockIdx.x * GM;
    int tr = t >> 5;   // 0..7 (warp-uniform)
    int tc = t & 31;   // 0..31

    float4 acc[8];
#pragma unroll
    for (int i = 0; i < 8; i++) acc[i] = make_float4(0.f, 0.f, 0.f, 0.f);

    for (int k0 = 0; k0 < DD; k0 += 32) {
        // stage A tile [64 rows x 32 k] transposed into As[k][m]
#pragma unroll
        for (int q = 0; q < 2; q++) {
            int id = q * 256 + t;      // 0..511
            int r  = id >> 3;          // 0..63
            int kq = id & 7;           // float4 within 32-k row
            int gm = m0 + r;
            float4 v = make_float4(0.f, 0.f, 0.f, 0.f);
            if (gm < NN) v = *(const float4*)&A[(size_t)gm * DD + k0 + kq * 4];
            As[kq * 4 + 0][r] = v.x;
            As[kq * 4 + 1][r] = v.y;
            As[kq * 4 + 2][r] = v.z;
            As[kq * 4 + 3][r] = v.w;
        }
        // stage W tile [32 k x 128 n]
#pragma unroll
        for (int q = 0; q < 4; q++) {
            int id = q * 256 + t;      // 0..1023
            int kr = id >> 5;          // 0..31
            int cq = id & 31;          // 0..31
            *(float4*)&Ws[kr][cq * 4] =
                *(const float4*)&W[(size_t)(k0 + kr) * DD + cq * 4];
        }
        __syncthreads();

#pragma unroll
        for (int kk = 0; kk < 32; kk++) {
            float4 w = *(const float4*)&Ws[kk][tc * 4];
            float4 a03 = *(const float4*)&As[kk][tr * 8];      // broadcast
            float4 a47 = *(const float4*)&As[kk][tr * 8 + 4];  // broadcast
            float am[8] = {a03.x, a03.y, a03.z, a03.w,
                           a47.x, a47.y, a47.z, a47.w};
#pragma unroll
            for (int i = 0; i < 8; i++) {
                acc[i].x += am[i] * w.x;
                acc[i].y += am[i] * w.y;
                acc[i].z += am[i] * w.z;
                acc[i].w += am[i] * w.w;
            }
        }
        __syncthreads();
    }

#pragma unroll
    for (int i = 0; i < 8; i++) {
        int gm = m0 + tr * 8 + i;
        if (gm < NN) {
            float ds = (layer == 0) ? 1.f : g_dis[gm];
            uint2 pk;
            pk.x = pack_bf(ds * acc[i].x, ds * acc[i].y);
            pk.y = pack_bf(ds * acc[i].z, ds * acc[i].w);
            *(uint2*)&g_bh[(size_t)gm * 64 + tc * 2] = pk;
        }
    }
}

// ---------------- aggregation (bf16 gathers, unroll-8/4 MLP) ----------------
// mode 0 (g_bh holds raw xw):  o = relu(dis[c]*(dis[c]*y[c] + sum dis[r]*y[r]) + b)
// mode 1 (g_bh holds dis*xw):  o = relu(dis[c]*(y[c] + sum y[r]) + b)
__global__ void __launch_bounds__(256) k_agg(const float* __restrict__ bias,
                                             int mode) {
    int w = (blockIdx.x * blockDim.x + threadIdx.x) >> 5;
    int lane = threadIdx.x & 31;
    if (w >= NN) return;
    float ds = g_dis[w];

    uint2 sv = *(const uint2*)&g_bh[(size_t)w * 64 + lane * 2];
    float2 s0 = unpack_bf(sv.x), s1 = unpack_bf(sv.y);
    float4 a0 = make_float4(s0.x, s0.y, s1.x, s1.y);   // self-loop term
    if (mode == 0) { a0.x *= ds; a0.y *= ds; a0.z *= ds; a0.w *= ds; }
    float4 a1 = make_float4(0.f, 0.f, 0.f, 0.f);
    float4 a2 = make_float4(0.f, 0.f, 0.f, 0.f);
    float4 a3 = make_float4(0.f, 0.f, 0.f, 0.f);

    int p = g_off[w];
    int e2 = g_off[w + 1];
    // unroll-8 main loop: 8 independent LDG.64 in flight per warp
    for (; p + 7 < e2; p += 8) {
        int rr[8];
#pragma unroll
        for (int j = 0; j < 8; j++) rr[j] = g_csr[p + j];
        uint2 uu[8];
#pragma unroll
        for (int j = 0; j < 8; j++)
            uu[j] = *(const uint2*)&g_bh[(size_t)rr[j] * 64 + lane * 2];
#pragma unroll
        for (int j = 0; j < 8; j++) {
            float d = (mode == 0) ? g_dis[rr[j]] : 1.f;
            float2 fa = unpack_bf(uu[j].x), fb = unpack_bf(uu[j].y);
            float4* ac = (j & 3) == 0 ? &a0 : (j & 3) == 1 ? &a1
                       : (j & 3) == 2 ? &a2 : &a3;
            ac->x += d * fa.x; ac->y += d * fa.y;
            ac->z += d * fb.x; ac->w += d * fb.y;
        }
    }
    // unroll-4 tail
    if (p + 3 < e2) {
        int rr[4];
#pragma unroll
        for (int j = 0; j < 4; j++) rr[j] = g_csr[p + j];
        uint2 uu[4];
#pragma unroll
        for (int j = 0; j < 4; j++)
            uu[j] = *(const uint2*)&g_bh[(size_t)rr[j] * 64 + lane * 2];
#pragma unroll
        for (int j = 0; j < 4; j++) {
            float d = (mode == 0) ? g_dis[rr[j]] : 1.f;
            float2 fa = unpack_bf(uu[j].x), fb = unpack_bf(uu[j].y);
            float4* ac = j == 0 ? &a0 : j == 1 ? &a1 : j == 2 ? &a2 : &a3;
            ac->x += d * fa.x; ac->y += d * fa.y;
            ac->z += d * fb.x; ac->w += d * fb.y;
        }
        p += 4;
    }
    for (; p < e2; p++) {
        int r0 = g_csr[p];
        uint2 u0 = *(const uint2*)&g_bh[(size_t)r0 * 64 + lane * 2];
        float2 f0a = unpack_bf(u0.x), f0b = unpack_bf(u0.y);
        float d0 = (mode == 0) ? g_dis[r0] : 1.f;
        a0.x += d0 * f0a.x; a0.y += d0 * f0a.y;
        a0.z += d0 * f0b.x; a0.w += d0 * f0b.y;
    }
    float4 b = ((const float4*)bias)[lane];
    float4 o;
    o.x = fmaxf(ds * ((a0.x + a1.x) + (a2.x + a3.x)) + b.x, 0.f);
    o.y = fmaxf(ds * ((a0.y + a1.y) + (a2.y + a3.y)) + b.y, 0.f);
    o.z = fmaxf(ds * ((a0.z + a1.z) + (a2.z + a3.z)) + b.z, 0.f);
    o.w = fmaxf(ds * ((a0.w + a1.w) + (a2.w + a3.w)) + b.w, 0.f);
    ((float4*)g_buf1)[(size_t)w * 32 + lane] = o;
}

// ---------------- fused pool + FC + log_softmax (per-graph independent) -----
__global__ void k_poolhead(const void* batch,
                           const float* __restrict__ Wfc,
                           const float* __restrict__ bfc,
                           float* __restrict__ out) {
    __shared__ float red[4][DD];
    __shared__ float pool[DD];
    __shared__ float lg[NC];
    int g = blockIdx.x;
    int is64 = (g_anyodd == 0);
    int lo = 0, hi = NN;
    while (lo < hi) {
        int mid = (lo + hi) >> 1;
        if (ld_idx(batch, mid, is64) < g) lo = mid + 1; else hi = mid;
    }
    int start = lo;
    hi = NN;
    while (lo < hi) {
        int mid = (lo + hi) >> 1;
        if (ld_idx(batch, mid, is64) <= g) lo = mid + 1; else hi = mid;
    }
    int end = lo;

    int d = threadIdx.x & 127;
    int rg = threadIdx.x >> 7;   // 0..3
    const float* __restrict__ h = g_buf1;
    float s = 0.f;
    for (int i = start + rg; i < end; i += 4) s += h[(size_t)i * DD + d];
    red[rg][d] = s;
    __syncthreads();
    if (rg == 0) {
        float inv = 1.f / fmaxf((float)(end - start), 1.f);
        pool[d] = ((red[0][d] + red[1][d]) + (red[2][d] + red[3][d])) * inv;
    }
    __syncthreads();
    if (threadIdx.x < NC) {
        int c = threadIdx.x;
        float acc = bfc[c];
#pragma unroll 4
        for (int dd2 = 0; dd2 < DD; dd2++)
            acc += pool[dd2] * Wfc[dd2 * NC + c];
        lg[c] = acc;
    }
    __syncthreads();
    if (threadIdx.x < NC) {
        int c = threadIdx.x;
        float m = -1e30f;
#pragma unroll
        for (int k = 0; k < NC; k++) m = fmaxf(m, lg[k]);
        float sum = 0.f;
#pragma unroll
        for (int k = 0; k < NC; k++) sum += expf(lg[k] - m);
        out[g * NC + c] = lg[c] - m - logf(sum);
    }
}

// ---------------- launch ----------------------------------------------------
extern "C" void kernel_launch(void* const* d_in, const int* in_sizes, int n_in,
                              void* d_out, int out_size) {
    (void)in_sizes; (void)n_in; (void)out_size;
    const float* x   = (const float*)d_in[0];
    const void*  ei  = d_in[1];
    const void*  bat = d_in[2];
    const float* W1  = (const float*)d_in[3];
    const float* b1  = (const float*)d_in[4];
    const float* W2  = (const float*)d_in[5];
    const float* b2  = (const float*)d_in[6];
    const float* Wfc = (const float*)d_in[7];
    const float* bfc = (const float*)d_in[8];
    float* out = (float*)d_out;

    // Side stream + events, created once on the (uncaptured) first call and
    // reused thereafter; the launched work is identical on every call.
    static cudaStream_t s2 = nullptr;
    static cudaEvent_t ev_fork = nullptr, ev_join = nullptr;
    if (s2 == nullptr) {
        cudaStreamCreateWithFlags(&s2, cudaStreamNonBlocking);
        cudaEventCreateWithFlags(&ev_fork, cudaEventDisableTiming);
        cudaEventCreateWithFlags(&ev_join, cudaEventDisableTiming);
    }

    int gblocks = (NN + GM - 1) / GM;   // 782

    // fork: GEMM1 (raw xw, no setup dependency) runs on s2 in parallel with
    // the CSR-build chain on the main stream.
    cudaEventRecord(ev_fork, 0);
    cudaStreamWaitEvent(s2, ev_fork, 0);
    k_gemm<<<gblocks, 256, 0, s2>>>(x, W1, 0);          // xw1 -> g_bh (raw)
    cudaEventRecord(ev_join, s2);

    k_init<<<NB, 256>>>(ei);
    k_deg<<<(NE + 255) / 256, 256>>>(ei);
    k_scanA<<<NB, 256>>>();
    k_scanB<<<1, 256>>>();
    k_scanC<<<NB, 256>>>();
    k_scatter<<<(NE + 255) / 256, 256>>>(ei);

    // join: agg1 needs CSR + dis (main stream) AND g_bh (s2)
    cudaStreamWaitEvent(0, ev_join, 0);

    k_agg<<<(NN * 32 + 255) / 256, 256>>>(b1, 0);       // h1 -> buf1
    k_gemm<<<gblocks, 256>>>(x, W2, 1);                 // dis*xw2 -> g_bh
    k_agg<<<(NN * 32 + 255) / 256, 256>>>(b2, 1);       // h2 -> buf1

    k_poolhead<<<NG, 512>>>(bat, Wfc, bfc, out);
}

// round 15
// speedup vs baseline: 1.2046x; 1.0626x over previous
#include <cuda_runtime.h>
#include <cuda_bf16.h>
#include <cuda_fp16.h>
#include <cstdint>

#define NN 50000
#define NE 800000
#define DD 128
#define NC 10
#define NG 64
#define NB 196   // ceil(NN/256)

// ---------------- scratch (static device globals; no runtime alloc) --------
__device__ unsigned g_bh[NN * DD / 2];  // GEMM output y as bf16x2 (8B/4 dims)
__device__ float g_buf1[NN * DD];       // aggregation output h' (relu, fp32)
__device__ float g_dis[NN];
__device__ int   g_deg[NN];
__device__ int   g_off[NN + 1];
__device__ int   g_cur[NN];
__device__ int   g_csr[NE];
__device__ int   g_bsum[NB];
__device__ int   g_boff[NB];
__device__ int   g_anyodd;          // 0 => indices are int64, nonzero => int32

__device__ __forceinline__ int ld_idx(const void* p, long long i, int is64) {
    return is64 ? (int)((const long long*)p)[i] : ((const int*)p)[i];
}
__device__ __forceinline__ unsigned pack_bf(float a, float b) {
    __nv_bfloat162 h = __floats2bfloat162_rn(a, b);
    return *(unsigned*)&h;
}
__device__ __forceinline__ float2 unpack_bf(unsigned u) {
    return __bfloat1622float2(*(__nv_bfloat162*)&u);
}

// ---------------- setup: zero deg + dtype detect (fused) --------------------
__global__ void k_init(const void* ei) {
    int i = blockIdx.x * blockDim.x + threadIdx.x;
    if (i < NN) g_deg[i] = 0;
    if (blockIdx.x == 0) {
        __shared__ int sm[256];
        int any = 0;
        for (int j = threadIdx.x; j < 4096; j += 256)
            any |= ((const int*)ei)[2 * j + 1];
        sm[threadIdx.x] = any;
        __syncthreads();
        for (int s = 128; s > 0; s >>= 1) {
            if (threadIdx.x < s) sm[threadIdx.x] |= sm[threadIdx.x + s];
            __syncthreads();
        }
        if (threadIdx.x == 0) g_anyodd = sm[0];
    }
}

// 4 edges per thread, int4 loads (NE % 4 == 0)
__global__ void k_deg(const void* ei) {
    int e0 = (blockIdx.x * blockDim.x + threadIdx.x) * 4;
    if (e0 >= NE) return;
    int c0, c1, c2, c3;
    if (g_anyodd == 0) {   // int64 indices
        const int4* q = (const int4*)((const long long*)ei + NE + e0);
        int4 a = q[0], b = q[1];
        c0 = a.x; c1 = a.z; c2 = b.x; c3 = b.z;
    } else {               // int32 indices
        int4 a = *(const int4*)((const int*)ei + NE + e0);
        c0 = a.x; c1 = a.y; c2 = a.z; c3 = a.w;
    }
    atomicAdd(&g_deg[c0], 1);
    atomicAdd(&g_deg[c1], 1);
    atomicAdd(&g_deg[c2], 1);
    atomicAdd(&g_deg[c3], 1);
}

// ---------------- 3-stage parallel scan of g_deg ----------------------------
__global__ void k_scanA() {
    __shared__ int sm[256];
    int t = threadIdx.x;
    int i = blockIdx.x * 256 + t;
    sm[t] = (i < NN) ? g_deg[i] : 0;
    __syncthreads();
    for (int s = 128; s > 0; s >>= 1) {
        if (t < s) sm[t] += sm[t + s];
        __syncthreads();
    }
    if (t == 0) g_bsum[blockIdx.x] = sm[0];
}

__global__ void k_scanB() {
    __shared__ int sm[256];
    int t = threadIdx.x;
    int v = (t < NB) ? g_bsum[t] : 0;
    sm[t] = v;
    __syncthreads();
    for (int off = 1; off < 256; off <<= 1) {
        int u = (t >= off) ? sm[t - off] : 0;
        __syncthreads();
        sm[t] += u;
        __syncthreads();
    }
    if (t < NB) g_boff[t] = sm[t] - v;   // exclusive
}

__global__ void k_scanC() {
    __shared__ int sm[256];
    int t = threadIdx.x;
    int i = blockIdx.x * 256 + t;
    int d = (i < NN) ? g_deg[i] : 0;
    sm[t] = d;
    __syncthreads();
    for (int off = 1; off < 256; off <<= 1) {
        int u = (t >= off) ? sm[t - off] : 0;
        __syncthreads();
        sm[t] += u;
        __syncthreads();
    }
    int off = g_boff[blockIdx.x] + sm[t] - d;   // exclusive prefix
    if (i < NN) {
        g_off[i] = off;
        g_cur[i] = off;
        g_dis[i] = rsqrtf((float)(d + 1));      // +1 self-loop
    }
    if (i == NN - 1) g_off[NN] = off + d;
}

// 4 edges per thread, int4 loads
__global__ void k_scatter(const void* ei) {
    int e0 = (blockIdx.x * blockDim.x + threadIdx.x) * 4;
    if (e0 >= NE) return;
    int r[4], c[4];
    if (g_anyodd == 0) {
        const int4* qr = (const int4*)((const long long*)ei + e0);
        const int4* qc = (const int4*)((const long long*)ei + NE + e0);
        int4 a = qr[0], b = qr[1];
        r[0] = a.x; r[1] = a.z; r[2] = b.x; r[3] = b.z;
        a = qc[0]; b = qc[1];
        c[0] = a.x; c[1] = a.z; c[2] = b.x; c[3] = b.z;
    } else {
        int4 a = *(const int4*)((const int*)ei + e0);
        r[0] = a.x; r[1] = a.y; r[2] = a.z; r[3] = a.w;
        a = *(const int4*)((const int*)ei + NE + e0);
        c[0] = a.x; c[1] = a.y; c[2] = a.z; c[3] = a.w;
    }
#pragma unroll
    for (int j = 0; j < 4; j++) {
        int pos = atomicAdd(&g_cur[c[j]], 1);
        g_csr[pos] = r[j];
    }
}

// ---------------- HFMA2 GEMM: k-paired half2, bf16 output -------------------
// acc2[m][n] channels hold partial sums for (even k, odd k); horizontal add
// at the end. fp16 accumulation error ~2e-3/elem, attenuated ~1e4x by the
// downstream contraction+pooling (empirically verified with bf16 storage).
// layer==0: A = x, stores RAW xw (no dis).  layer==1: A = g_buf1, dis-scaled.
#define GM 64
__global__ void __launch_bounds__(256) k_gemm(const float* __restrict__ x_ext,
                                              const float* __restrict__ W,
                                              int layer) {
    __shared__ __half2 As2[16][68];    // [kpair][m], 272B rows (16B-aligned)
    __shared__ __half2 Ws2[16][132];   // [kpair][n], 528B rows (16B-aligned)
    const float* __restrict__ A = (layer == 0) ? x_ext : g_buf1;

    int t = threadIdx.x;
    int m0 = blockIdx.x * GM;
    int tr = t >> 5;   // 0..7 (warp-uniform)
    int tc = t & 31;   // 0..31

    __half2 acc2[8][4];
    __half2 z2 = __float2half2_rn(0.f);
#pragma unroll
    for (int i = 0; i < 8; i++)
#pragma unroll
        for (int n = 0; n < 4; n++) acc2[i][n] = z2;

    for (int k0 = 0; k0 < DD; k0 += 32) {
        // stage A tile [64 m x 32 k] -> As2[kp][m] (k-paired half2)
#pragma unroll
        for (int q = 0; q < 2; q++) {
            int id = q * 256 + t;      // 0..511
            int r  = id >> 3;          // m 0..63
            int kq = id & 7;           // float4 within 32-k row
            int gm = m0 + r;
            float4 v = make_float4(0.f, 0.f, 0.f, 0.f);
            if (gm < NN) v = *(const float4*)&A[(size_t)gm * DD + k0 + kq * 4];
            As2[kq * 2 + 0][r] = __floats2half2_rn(v.x, v.y);
            As2[kq * 2 + 1][r] = __floats2half2_rn(v.z, v.w);
        }
        // stage W tile [32 k x 128 n] -> Ws2[kp][n] (k-paired across 2 rows)
#pragma unroll
        for (int q = 0; q < 2; q++) {
            int id = q * 256 + t;      // 0..511
            int kp = id >> 5;          // 0..15
            int c4 = id & 31;          // 0..31
            float4 w0 = *(const float4*)&W[(size_t)(k0 + 2 * kp) * DD + c4 * 4];
            float4 w1 = *(const float4*)&W[(size_t)(k0 + 2 * kp + 1) * DD + c4 * 4];
            __half2 h[4];
            h[0] = __floats2half2_rn(w0.x, w1.x);
            h[1] = __floats2half2_rn(w0.y, w1.y);
            h[2] = __floats2half2_rn(w0.z, w1.z);
            h[3] = __floats2half2_rn(w0.w, w1.w);
            *(uint4*)&Ws2[kp][c4 * 4] = *(uint4*)h;
        }
        __syncthreads();

#pragma unroll
        for (int kp = 0; kp < 16; kp++) {
            __half2 w2[4], a2[8];
            *(uint4*)w2       = *(const uint4*)&Ws2[kp][tc * 4];   // 4 n
            *(uint4*)&a2[0]   = *(const uint4*)&As2[kp][tr * 8];   // m 0..3 (bcast)
            *(uint4*)&a2[4]   = *(const uint4*)&As2[kp][tr * 8 + 4]; // m 4..7
#pragma unroll
            for (int i = 0; i < 8; i++)
#pragma unroll
                for (int n = 0; n < 4; n++)
                    acc2[i][n] = __hfma2(a2[i], w2[n], acc2[i][n]);
        }
        __syncthreads();
    }

    // epilogue: horizontal add channels, scale by dis, pack bf16
#pragma unroll
    for (int i = 0; i < 8; i++) {
        int gm = m0 + tr * 8 + i;
        if (gm < NN) {
            float ds = (layer == 0) ? 1.f : g_dis[gm];
            float2 p0 = __half22float2(acc2[i][0]);
            float2 p1 = __half22float2(acc2[i][1]);
            float2 p2 = __half22float2(acc2[i][2]);
            float2 p3 = __half22float2(acc2[i][3]);
            uint2 pk;
            pk.x = pack_bf(ds * (p0.x + p0.y), ds * (p1.x + p1.y));
            pk.y = pack_bf(ds * (p2.x + p2.y), ds * (p3.x + p3.y));
            *(uint2*)&g_bh[(size_t)gm * 64 + tc * 2] = pk;
        }
    }
}

// ---------------- aggregation (bf16 gathers, unroll-8/4 MLP) ----------------
// mode 0 (g_bh holds raw xw):  o = relu(dis[c]*(dis[c]*y[c] + sum dis[r]*y[r]) + b)
// mode 1 (g_bh holds dis*xw):  o = relu(dis[c]*(y[c] + sum y[r]) + b)
__global__ void __launch_bounds__(256) k_agg(const float* __restrict__ bias,
                                             int mode) {
    int w = (blockIdx.x * blockDim.x + threadIdx.x) >> 5;
    int lane = threadIdx.x & 31;
    if (w >= NN) return;
    float ds = g_dis[w];

    uint2 sv = *(const uint2*)&g_bh[(size_t)w * 64 + lane * 2];
    float2 s0 = unpack_bf(sv.x), s1 = unpack_bf(sv.y);
    float4 a0 = make_float4(s0.x, s0.y, s1.x, s1.y);   // self-loop term
    if (mode == 0) { a0.x *= ds; a0.y *= ds; a0.z *= ds; a0.w *= ds; }
    float4 a1 = make_float4(0.f, 0.f, 0.f, 0.f);
    float4 a2 = make_float4(0.f, 0.f, 0.f, 0.f);
    float4 a3 = make_float4(0.f, 0.f, 0.f, 0.f);

    int p = g_off[w];
    int e2 = g_off[w + 1];
    // unroll-8 main loop: 8 independent LDG.64 in flight per warp
    for (; p + 7 < e2; p += 8) {
        int rr[8];
#pragma unroll
        for (int j = 0; j < 8; j++) rr[j] = g_csr[p + j];
        uint2 uu[8];
#pragma unroll
        for (int j = 0; j < 8; j++)
            uu[j] = *(const uint2*)&g_bh[(size_t)rr[j] * 64 + lane * 2];
#pragma unroll
        for (int j = 0; j < 8; j++) {
            float d = (mode == 0) ? g_dis[rr[j]] : 1.f;
            float2 fa = unpack_bf(uu[j].x), fb = unpack_bf(uu[j].y);
            float4* ac = (j & 3) == 0 ? &a0 : (j & 3) == 1 ? &a1
                       : (j & 3) == 2 ? &a2 : &a3;
            ac->x += d * fa.x; ac->y += d * fa.y;
            ac->z += d * fb.x; ac->w += d * fb.y;
        }
    }
    // unroll-4 tail
    if (p + 3 < e2) {
        int rr[4];
#pragma unroll
        for (int j = 0; j < 4; j++) rr[j] = g_csr[p + j];
        uint2 uu[4];
#pragma unroll
        for (int j = 0; j < 4; j++)
            uu[j] = *(const uint2*)&g_bh[(size_t)rr[j] * 64 + lane * 2];
#pragma unroll
        for (int j = 0; j < 4; j++) {
            float d = (mode == 0) ? g_dis[rr[j]] : 1.f;
            float2 fa = unpack_bf(uu[j].x), fb = unpack_bf(uu[j].y);
            float4* ac = j == 0 ? &a0 : j == 1 ? &a1 : j == 2 ? &a2 : &a3;
            ac->x += d * fa.x; ac->y += d * fa.y;
            ac->z += d * fb.x; ac->w += d * fb.y;
        }
        p += 4;
    }
    for (; p < e2; p++) {
        int r0 = g_csr[p];
        uint2 u0 = *(const uint2*)&g_bh[(size_t)r0 * 64 + lane * 2];
        float2 f0a = unpack_bf(u0.x), f0b = unpack_bf(u0.y);
        float d0 = (mode == 0) ? g_dis[r0] : 1.f;
        a0.x += d0 * f0a.x; a0.y += d0 * f0a.y;
        a0.z += d0 * f0b.x; a0.w += d0 * f0b.y;
    }
    float4 b = ((const float4*)bias)[lane];
    float4 o;
    o.x = fmaxf(ds * ((a0.x + a1.x) + (a2.x + a3.x)) + b.x, 0.f);
    o.y = fmaxf(ds * ((a0.y + a1.y) + (a2.y + a3.y)) + b.y, 0.f);
    o.z = fmaxf(ds * ((a0.z + a1.z) + (a2.z + a3.z)) + b.z, 0.f);
    o.w = fmaxf(ds * ((a0.w + a1.w) + (a2.w + a3.w)) + b.w, 0.f);
    ((float4*)g_buf1)[(size_t)w * 32 + lane] = o;
}

// ---------------- fused pool + FC + log_softmax (per-graph independent) -----
__global__ void k_poolhead(const void* batch,
                           const float* __restrict__ Wfc,
                           const float* __restrict__ bfc,
                           float* __restrict__ out) {
    __shared__ float red[4][DD];
    __shared__ float pool[DD];
    __shared__ float lg[NC];
    int g = blockIdx.x;
    int is64 = (g_anyodd == 0);
    int lo = 0, hi = NN;
    while (lo < hi) {
        int mid = (lo + hi) >> 1;
        if (ld_idx(batch, mid, is64) < g) lo = mid + 1; else hi = mid;
    }
    int start = lo;
    hi = NN;
    while (lo < hi) {
        int mid = (lo + hi) >> 1;
        if (ld_idx(batch, mid, is64) <= g) lo = mid + 1; else hi = mid;
    }
    int end = lo;

    int d = threadIdx.x & 127;
    int rg = threadIdx.x >> 7;   // 0..3
    const float* __restrict__ h = g_buf1;
    float s = 0.f;
    for (int i = start + rg; i < end; i += 4) s += h[(size_t)i * DD + d];
    red[rg][d] = s;
    __syncthreads();
    if (rg == 0) {
        float inv = 1.f / fmaxf((float)(end - start), 1.f);
        pool[d] = ((red[0][d] + red[1][d]) + (red[2][d] + red[3][d])) * inv;
    }
    __syncthreads();
    if (threadIdx.x < NC) {
        int c = threadIdx.x;
        float acc = bfc[c];
#pragma unroll 4
        for (int dd2 = 0; dd2 < DD; dd2++)
            acc += pool[dd2] * Wfc[dd2 * NC + c];
        lg[c] = acc;
    }
    __syncthreads();
    if (threadIdx.x < NC) {
        int c = threadIdx.x;
        float m = -1e30f;
#pragma unroll
        for (int k = 0; k < NC; k++) m = fmaxf(m, lg[k]);
        float sum = 0.f;
#pragma unroll
        for (int k = 0; k < NC; k++) sum += expf(lg[k] - m);
        out[g * NC + c] = lg[c] - m - logf(sum);
    }
}

// ---------------- launch ----------------------------------------------------
extern "C" void kernel_launch(void* const* d_in, const int* in_sizes, int n_in,
                              void* d_out, int out_size) {
    (void)in_sizes; (void)n_in; (void)out_size;
    const float* x   = (const float*)d_in[0];
    const void*  ei  = d_in[1];
    const void*  bat = d_in[2];
    const float* W1  = (const float*)d_in[3];
    const float* b1  = (const float*)d_in[4];
    const float* W2  = (const float*)d_in[5];
    const float* b2  = (const float*)d_in[6];
    const float* Wfc = (const float*)d_in[7];
    const float* bfc = (const float*)d_in[8];
    float* out = (float*)d_out;

    // Side stream + events, created once on the (uncaptured) first call and
    // reused thereafter; the launched work is identical on every call.
    static cudaStream_t s2 = nullptr;
    static cudaEvent_t ev_fork = nullptr, ev_join = nullptr;
    if (s2 == nullptr) {
        cudaStreamCreateWithFlags(&s2, cudaStreamNonBlocking);
        cudaEventCreateWithFlags(&ev_fork, cudaEventDisableTiming);
        cudaEventCreateWithFlags(&ev_join, cudaEventDisableTiming);
    }

    int gblocks = (NN + GM - 1) / GM;   // 782
    int eblocks = (NE / 4 + 255) / 256; // 782

    // fork: GEMM1 (raw xw, no setup dependency) runs on s2 in parallel with
    // the CSR-build chain on the main stream.
    cudaEventRecord(ev_fork, 0);
    cudaStreamWaitEvent(s2, ev_fork, 0);
    k_gemm<<<gblocks, 256, 0, s2>>>(x, W1, 0);          // xw1 -> g_bh (raw)
    cudaEventRecord(ev_join, s2);

    k_init<<<NB, 256>>>(ei);
    k_deg<<<eblocks, 256>>>(ei);
    k_scanA<<<NB, 256>>>();
    k_scanB<<<1, 256>>>();
    k_scanC<<<NB, 256>>>();
    k_scatter<<<eblocks, 256>>>(ei);

    // join: agg1 needs CSR + dis (main stream) AND g_bh (s2)
    cudaStreamWaitEvent(0, ev_join, 0);

    k_agg<<<(NN * 32 + 255) / 256, 256>>>(b1, 0);       // h1 -> buf1
    k_gemm<<<gblocks, 256>>>(x, W2, 1);                 // dis*xw2 -> g_bh
    k_agg<<<(NN * 32 + 255) / 256, 256>>>(b2, 1);       // h2 -> buf1

    k_poolhead<<<NG, 512>>>(bat, Wfc, bfc, out);
}

// round 17
// speedup vs baseline: 1.2160x; 1.0094x over previous
#include <cuda_runtime.h>
#include <cuda_bf16.h>
#include <cuda_fp16.h>
#include <cstdint>

#define NN 50000
#define NE 800000
#define DD 128
#define NC 10
#define NG 64
#define NB 196   // ceil(NN/256)

// ---------------- scratch (static device globals; no runtime alloc) --------
__device__ unsigned g_bh[NN * DD / 2];  // GEMM output y as bf16x2 (8B/4 dims)
__device__ unsigned g_h1[NN * DD / 2];  // agg output h as half2x2 (8B/4 dims)
__device__ float g_dis[NN];
__device__ int   g_deg[NN];
__device__ int   g_off[NN + 1];
__device__ int   g_cur[NN];
__device__ int   g_csr[NE];
__device__ volatile int g_agg[NB];
__device__ volatile int g_incl[NB];
__device__ volatile int g_flag[NB];
__device__ int   g_anyodd;          // 0 => indices are int64, nonzero => int32

__device__ __forceinline__ int ld_idx(const void* p, long long i, int is64) {
    return is64 ? (int)((const long long*)p)[i] : ((const int*)p)[i];
}
__device__ __forceinline__ unsigned pack_bf(float a, float b) {
    __nv_bfloat162 h = __floats2bfloat162_rn(a, b);
    return *(unsigned*)&h;
}
__device__ __forceinline__ float2 unpack_bf(unsigned u) {
    return __bfloat1622float2(*(__nv_bfloat162*)&u);
}
__device__ __forceinline__ unsigned pack_h(float a, float b) {
    __half2 h = __floats2half2_rn(a, b);
    return *(unsigned*)&h;
}
__device__ __forceinline__ float2 unpack_h(unsigned u) {
    return __half22float2(*(__half2*)&u);
}

// ---------------- dtype detect (1 block) ------------------------------------
__global__ void k_detect(const void* ei) {
    __shared__ int sm[256];
    int any = 0;
    for (int j = threadIdx.x; j < 4096; j += 256)
        any |= ((const int*)ei)[2 * j + 1];
    sm[threadIdx.x] = any;
    __syncthreads();
    for (int s = 128; s > 0; s >>= 1) {
        if (threadIdx.x < s) sm[threadIdx.x] |= sm[threadIdx.x + s];
        __syncthreads();
    }
    if (threadIdx.x == 0) g_anyodd = sm[0];
}

// 4 edges per thread, int4 loads (NE % 4 == 0); also zeroes scan flags.
// g_deg is zero on entry (static init on first run; k_scan1 re-zeroes after).
__global__ void k_deg(const void* ei) {
    int tid = blockIdx.x * blockDim.x + threadIdx.x;
    if (tid < NB) g_flag[tid] = 0;
    int e0 = tid * 4;
    if (e0 >= NE) return;
    int c0, c1, c2, c3;
    if (g_anyodd == 0) {   // int64 indices
        const int4* q = (const int4*)((const long long*)ei + NE + e0);
        int4 a = q[0], b = q[1];
        c0 = a.x; c1 = a.z; c2 = b.x; c3 = b.z;
    } else {               // int32 indices
        int4 a = *(const int4*)((const int*)ei + NE + e0);
        c0 = a.x; c1 = a.y; c2 = a.z; c3 = a.w;
    }
    atomicAdd(&g_deg[c0], 1);
    atomicAdd(&g_deg[c1], 1);
    atomicAdd(&g_deg[c2], 1);
    atomicAdd(&g_deg[c3], 1);
}

// ---------------- single-pass decoupled-lookback scan -----------------------
// Produces g_off/g_cur/g_dis, and re-zeroes g_deg for the next replay.
__global__ void k_scan1() {
    __shared__ int sm[256];
    __shared__ int s_excl;
    int t = threadIdx.x;
    int b = blockIdx.x;
    int i = b * 256 + t;
    int d = (i < NN) ? g_deg[i] : 0;
    sm[t] = d;
    __syncthreads();
    for (int off = 1; off < 256; off <<= 1) {
        int u = (t >= off) ? sm[t - off] : 0;
        __syncthreads();
        sm[t] += u;
        __syncthreads();
    }
    int total = sm[255];
    if (t == 0) {
        if (b == 0) {
            g_incl[0] = total;
            __threadfence();
            g_flag[0] = 2;
            s_excl = 0;
        } else {
            g_agg[b] = total;
            __threadfence();
            g_flag[b] = 1;
            int excl = 0;
            for (int j = b - 1; j >= 0; j--) {
                int f;
                while ((f = g_flag[j]) == 0) { }
                if (f == 2) { excl += g_incl[j]; break; }
                excl += g_agg[j];
            }
            g_incl[b] = excl + total;
            __threadfence();
            g_flag[b] = 2;
            s_excl = excl;
        }
    }
    __syncthreads();
    int off = s_excl + sm[t] - d;   // exclusive prefix
    if (i < NN) {
        g_off[i] = off;
        g_cur[i] = off;
        g_dis[i] = rsqrtf((float)(d + 1));  // +1 self-loop
        g_deg[i] = 0;                       // reset for next replay
    }
    if (i == NN - 1) g_off[NN] = off + d;
}

// 4 edges per thread, int4 loads
__global__ void k_scatter(const void* ei) {
    int e0 = (blockIdx.x * blockDim.x + threadIdx.x) * 4;
    if (e0 >= NE) return;
    int r[4], c[4];
    if (g_anyodd == 0) {
        const int4* qr = (const int4*)((const long long*)ei + e0);
        const int4* qc = (const int4*)((const long long*)ei + NE + e0);
        int4 a = qr[0], b = qr[1];
        r[0] = a.x; r[1] = a.z; r[2] = b.x; r[3] = b.z;
        a = qc[0]; b = qc[1];
        c[0] = a.x; c[1] = a.z; c[2] = b.x; c[3] = b.z;
    } else {
        int4 a = *(const int4*)((const int*)ei + e0);
        r[0] = a.x; r[1] = a.y; r[2] = a.z; r[3] = a.w;
        a = *(const int4*)((const int*)ei + NE + e0);
        c[0] = a.x; c[1] = a.y; c[2] = a.z; c[3] = a.w;
    }
#pragma unroll
    for (int j = 0; j < 4; j++) {
        int pos = atomicAdd(&g_cur[c[j]], 1);
        g_csr[pos] = r[j];
    }
}

// ---------------- HFMA2 GEMM: k-paired half2, bf16 output -------------------
// layer==0: A = x (fp32), stores RAW xw.  layer==1: A = g_h1 (half), dis-scaled.
#define GM 64
__global__ void __launch_bounds__(256) k_gemm(const float* __restrict__ x_ext,
                                              const float* __restrict__ W,
                                              int layer) {
    __shared__ __half2 As2[16][68];    // [kpair][m], 272B rows (16B-aligned)
    __shared__ __half2 Ws2[16][132];   // [kpair][n], 528B rows (16B-aligned)

    int t = threadIdx.x;
    int m0 = blockIdx.x * GM;
    int tr = t >> 5;   // 0..7 (warp-uniform)
    int tc = t & 31;   // 0..31

    __half2 acc2[8][4];
    __half2 z2 = __float2half2_rn(0.f);
#pragma unroll
    for (int i = 0; i < 8; i++)
#pragma unroll
        for (int n = 0; n < 4; n++) acc2[i][n] = z2;

    for (int k0 = 0; k0 < DD; k0 += 32) {
        // stage A tile [64 m x 32 k] -> As2[kp][m] (k-paired half2)
#pragma unroll
        for (int q = 0; q < 2; q++) {
            int id = q * 256 + t;      // 0..511
            int r  = id >> 3;          // m 0..63
            int kq = id & 7;           // 4-k group within 32-k row
            int gm = m0 + r;
            if (layer == 0) {
                float4 v = make_float4(0.f, 0.f, 0.f, 0.f);
                if (gm < NN)
                    v = *(const float4*)&x_ext[(size_t)gm * DD + k0 + kq * 4];
                As2[kq * 2 + 0][r] = __floats2half2_rn(v.x, v.y);
                As2[kq * 2 + 1][r] = __floats2half2_rn(v.z, v.w);
            } else {
                uint2 v = make_uint2(0u, 0u);
                if (gm < NN)
                    v = *(const uint2*)&g_h1[(size_t)gm * 64 + (k0 + kq * 4) / 2];
                As2[kq * 2 + 0][r] = *(__half2*)&v.x;   // (k0,k1) pre-packed
                As2[kq * 2 + 1][r] = *(__half2*)&v.y;   // (k2,k3)
            }
        }
        // stage W tile [32 k x 128 n] -> Ws2[kp][n] (k-paired across 2 rows)
#pragma unroll
        for (int q = 0; q < 2; q++) {
            int id = q * 256 + t;      // 0..511
            int kp = id >> 5;          // 0..15
            int c4 = id & 31;          // 0..31
            float4 w0 = *(const float4*)&W[(size_t)(k0 + 2 * kp) * DD + c4 * 4];
            float4 w1 = *(const float4*)&W[(size_t)(k0 + 2 * kp + 1) * DD + c4 * 4];
            __half2 h[4];
            h[0] = __floats2half2_rn(w0.x, w1.x);
            h[1] = __floats2half2_rn(w0.y, w1.y);
            h[2] = __floats2half2_rn(w0.z, w1.z);
            h[3] = __floats2half2_rn(w0.w, w1.w);
            *(uint4*)&Ws2[kp][c4 * 4] = *(uint4*)h;
        }
        __syncthreads();

#pragma unroll
        for (int kp = 0; kp < 16; kp++) {
            __half2 w2[4], a2[8];
            *(uint4*)w2     = *(const uint4*)&Ws2[kp][tc * 4];     // 4 n
            *(uint4*)&a2[0] = *(const uint4*)&As2[kp][tr * 8];     // m 0..3
            *(uint4*)&a2[4] = *(const uint4*)&As2[kp][tr * 8 + 4]; // m 4..7
#pragma unroll
            for (int i = 0; i < 8; i++)
#pragma unroll
                for (int n = 0; n < 4; n++)
                    acc2[i][n] = __hfma2(a2[i], w2[n], acc2[i][n]);
        }
        __syncthreads();
    }

    // epilogue: horizontal add channels, scale by dis, pack bf16
#pragma unroll
    for (int i = 0; i < 8; i++) {
        int gm = m0 + tr * 8 + i;
        if (gm < NN) {
            float ds = (layer == 0) ? 1.f : g_dis[gm];
            float2 p0 = __half22float2(acc2[i][0]);
            float2 p1 = __half22float2(acc2[i][1]);
            float2 p2 = __half22float2(acc2[i][2]);
            float2 p3 = __half22float2(acc2[i][3]);
            uint2 pk;
            pk.x = pack_bf(ds * (p0.x + p0.y), ds * (p1.x + p1.y));
            pk.y = pack_bf(ds * (p2.x + p2.y), ds * (p3.x + p3.y));
            *(uint2*)&g_bh[(size_t)gm * 64 + tc * 2] = pk;
        }
    }
}

// ---------------- aggregation (bf16 gathers, unroll-8/4 MLP, fp16 out) ------
// mode 0 (g_bh raw xw):   o = relu(dis[c]*(dis[c]*y[c] + sum dis[r]*y[r]) + b)
// mode 1 (g_bh dis*xw):   o = relu(dis[c]*(y[c] + sum y[r]) + b)
__global__ void __launch_bounds__(256) k_agg(const float* __restrict__ bias,
                                             int mode) {
    int w = (blockIdx.x * blockDim.x + threadIdx.x) >> 5;
    int lane = threadIdx.x & 31;
    if (w >= NN) return;
    float ds = g_dis[w];

    uint2 sv = *(const uint2*)&g_bh[(size_t)w * 64 + lane * 2];
    float2 s0 = unpack_bf(sv.x), s1 = unpack_bf(sv.y);
    float4 a0 = make_float4(s0.x, s0.y, s1.x, s1.y);   // self-loop term
    if (mode == 0) { a0.x *= ds; a0.y *= ds; a0.z *= ds; a0.w *= ds; }
    float4 a1 = make_float4(0.f, 0.f, 0.f, 0.f);
    float4 a2 = make_float4(0.f, 0.f, 0.f, 0.f);
    float4 a3 = make_float4(0.f, 0.f, 0.f, 0.f);

    int p = g_off[w];
    int e2 = g_off[w + 1];
    // unroll-8 main loop: 8 independent LDG.64 in flight per warp
    for (; p + 7 < e2; p += 8) {
        int rr[8];
#pragma unroll
        for (int j = 0; j < 8; j++) rr[j] = g_csr[p + j];
        uint2 uu[8];
#pragma unroll
        for (int j = 0; j < 8; j++)
            uu[j] = *(const uint2*)&g_bh[(size_t)rr[j] * 64 + lane * 2];
#pragma unroll
        for (int j = 0; j < 8; j++) {
            float d = (mode == 0) ? g_dis[rr[j]] : 1.f;
            float2 fa = unpack_bf(uu[j].x), fb = unpack_bf(uu[j].y);
            float4* ac = (j & 3) == 0 ? &a0 : (j & 3) == 1 ? &a1
                       : (j & 3) == 2 ? &a2 : &a3;
            ac->x += d * fa.x; ac->y += d * fa.y;
            ac->z += d * fb.x; ac->w += d * fb.y;
        }
    }
    // unroll-4 tail
    if (p + 3 < e2) {
        int rr[4];
#pragma unroll
        for (int j = 0; j < 4; j++) rr[j] = g_csr[p + j];
        uint2 uu[4];
#pragma unroll
        for (int j = 0; j < 4; j++)
            uu[j] = *(const uint2*)&g_bh[(size_t)rr[j] * 64 + lane * 2];
#pragma unroll
        for (int j = 0; j < 4; j++) {
            float d = (mode == 0) ? g_dis[rr[j]] : 1.f;
            float2 fa = unpack_bf(uu[j].x), fb = unpack_bf(uu[j].y);
            float4* ac = j == 0 ? &a0 : j == 1 ? &a1 : j == 2 ? &a2 : &a3;
            ac->x += d * fa.x; ac->y += d * fa.y;
            ac->z += d * fb.x; ac->w += d * fb.y;
        }
        p += 4;
    }
    for (; p < e2; p++) {
        int r0 = g_csr[p];
        uint2 u0 = *(const uint2*)&g_bh[(size_t)r0 * 64 + lane * 2];
        float2 f0a = unpack_bf(u0.x), f0b = unpack_bf(u0.y);
        float d0 = (mode == 0) ? g_dis[r0] : 1.f;
        a0.x += d0 * f0a.x; a0.y += d0 * f0a.y;
        a0.z += d0 * f0b.x; a0.w += d0 * f0b.y;
    }
    float4 b = ((const float4*)bias)[lane];
    float ox = fmaxf(ds * ((a0.x + a1.x) + (a2.x + a3.x)) + b.x, 0.f);
    float oy = fmaxf(ds * ((a0.y + a1.y) + (a2.y + a3.y)) + b.y, 0.f);
    float oz = fmaxf(ds * ((a0.z + a1.z) + (a2.z + a3.z)) + b.z, 0.f);
    float ow = fmaxf(ds * ((a0.w + a1.w) + (a2.w + a3.w)) + b.w, 0.f);
    uint2 hv;
    hv.x = pack_h(ox, oy);
    hv.y = pack_h(oz, ow);
    *(uint2*)&g_h1[(size_t)w * 64 + lane * 2] = hv;
}

// ---------------- fused pool + FC + log_softmax (reads fp16 h) --------------
__global__ void k_poolhead(const void* batch,
                           const float* __restrict__ Wfc,
                           const float* __restrict__ bfc,
                           float* __restrict__ out) {
    __shared__ float red[4][DD];
    __shared__ float pool[DD];
    __shared__ float lg[NC];
    int g = blockIdx.x;
    int is64 = (g_anyodd == 0);
    int lo = 0, hi = NN;
    while (lo < hi) {
        int mid = (lo + hi) >> 1;
        if (ld_idx(batch, mid, is64) < g) lo = mid + 1; else hi = mid;
    }
    int start = lo;
    hi = NN;
    while (lo < hi) {
        int mid = (lo + hi) >> 1;
        if (ld_idx(batch, mid, is64) <= g) lo = mid + 1; else hi = mid;
    }
    int end = lo;

    int d = threadIdx.x & 127;
    int rg = threadIdx.x >> 7;   // 0..3
    const __half* __restrict__ h = (const __half*)g_h1;
    float s = 0.f;
    for (int i = start + rg; i < end; i += 4)
        s += __half2float(h[(size_t)i * DD + d]);
    red[rg][d] = s;
    __syncthreads();
    if (rg == 0) {
        float inv = 1.f / fmaxf((float)(end - start), 1.f);
        pool[d] = ((red[0][d] + red[1][d]) + (red[2][d] + red[3][d])) * inv;
    }
    __syncthreads();
    if (threadIdx.x < NC) {
        int c = threadIdx.x;
        float acc = bfc[c];
#pragma unroll 4
        for (int dd2 = 0; dd2 < DD; dd2++)
            acc += pool[dd2] * Wfc[dd2 * NC + c];
        lg[c] = acc;
    }
    __syncthreads();
    if (threadIdx.x < NC) {
        int c = threadIdx.x;
        float m = -1e30f;
#pragma unroll
        for (int k = 0; k < NC; k++) m = fmaxf(m, lg[k]);
        float sum = 0.f;
#pragma unroll
        for (int k = 0; k < NC; k++) sum += expf(lg[k] - m);
        out[g * NC + c] = lg[c] - m - logf(sum);
    }
}

// ---------------- launch ----------------------------------------------------
extern "C" void kernel_launch(void* const* d_in, const int* in_sizes, int n_in,
                              void* d_out, int out_size) {
    (void)in_sizes; (void)n_in; (void)out_size;
    const float* x   = (const float*)d_in[0];
    const void*  ei  = d_in[1];
    const void*  bat = d_in[2];
    const float* W1  = (const float*)d_in[3];
    const float* b1  = (const float*)d_in[4];
    const float* W2  = (const float*)d_in[5];
    const float* b2  = (const float*)d_in[6];
    const float* Wfc = (const float*)d_in[7];
    const float* bfc = (const float*)d_in[8];
    float* out = (float*)d_out;

    // Side stream + events, created once on the (uncaptured) first call and
    // reused thereafter; the launched work is identical on every call.
    static cudaStream_t s2 = nullptr;
    static cudaEvent_t ev_fork = nullptr, ev_join = nullptr;
    if (s2 == nullptr) {
        cudaStreamCreateWithFlags(&s2, cudaStreamNonBlocking);
        cudaEventCreateWithFlags(&ev_fork, cudaEventDisableTiming);
        cudaEventCreateWithFlags(&ev_join, cudaEventDisableTiming);
    }

    int gblocks = (NN + GM - 1) / GM;   // 782
    int eblocks = (NE / 4 + 255) / 256; // 782

    // fork: GEMM1 (raw xw, no setup dependency) runs on s2 in parallel with
    // the CSR-build chain on the main stream.
    cudaEventRecord(ev_fork, 0);
    cudaStreamWaitEvent(s2, ev_fork, 0);
    k_gemm<<<gblocks, 256, 0, s2>>>(x, W1, 0);          // xw1 -> g_bh (raw)
    cudaEventRecord(ev_join, s2);

    k_detect<<<1, 256>>>(ei);
    k_deg<<<eblocks, 256>>>(ei);
    k_scan1<<<NB, 256>>>();
    k_scatter<<<eblocks, 256>>>(ei);

    // join: agg1 needs CSR + dis (main stream) AND g_bh (s2)
    cudaStreamWaitEvent(0, ev_join, 0);

    k_agg<<<(NN * 32 + 255) / 256, 256>>>(b1, 0);       // h1 -> g_h1 (fp16)
    k_gemm<<<gblocks, 256>>>(x, W2, 1);                 // dis*xw2 -> g_bh
    k_agg<<<(NN * 32 + 255) / 256, 256>>>(b2, 1);       // h2 -> g_h1 (fp16)

    k_poolhead<<<NG, 512>>>(bat, Wfc, bfc, out);
}